// round 13
// baseline (speedup 1.0000x reference)
#include <cuda_runtime.h>
#include <cuda_bf16.h>
#include <math.h>
#include <stdint.h>

#define NN 10000
#define CC 128
#define HH 256
#define EE 320000

// ---------------- scratch (device globals; no allocation allowed) ------------
__device__ float g_hn  [NN * CC];    // LN1(h)
__device__ float g_PAB [NN * 512];   // [ hn@We1[0:128] | hn@We1[128:256] ]
__device__ float g_msum[NN * HH];    // segment sums (atomic target)
__device__ float g_cnt [NN];         // segment counts
__device__ float g_t1  [NN * HH];
__device__ float g_h1  [NN * CC];
__device__ float g_h2n [NN * CC];
__device__ float g_t2  [NN * HH];
__device__ __nv_bfloat16 g_Bbf[HH * HH];      // Bbf[n][k] = bf16(We2[k][n])
__device__ uint32_t g_m1f[(size_t)EE * 128];  // m1 in mma A-fragment layout (bf16x2)
__device__ float g_cc  [EE];                  // cutoff per edge

__device__ __forceinline__ float silu_f(float v) {
    return v / (1.0f + __expf(-v));
}

__device__ __forceinline__ uint32_t smem_u32(const void* p) {
    uint32_t a;
    asm("{ .reg .u64 t; cvta.to.shared.u64 t, %1; cvt.u32.u64 %0, t; }"
        : "=r"(a) : "l"(p));
    return a;
}
__device__ __forceinline__ void ldsm_x4(uint32_t& a0, uint32_t& a1,
                                        uint32_t& a2, uint32_t& a3, uint32_t addr) {
    asm volatile("ldmatrix.sync.aligned.m8n8.x4.shared.b16 {%0,%1,%2,%3}, [%4];"
        : "=r"(a0), "=r"(a1), "=r"(a2), "=r"(a3) : "r"(addr));
}
__device__ __forceinline__ void mma_bf16(float* d, uint32_t a0, uint32_t a1,
                                         uint32_t a2, uint32_t a3,
                                         uint32_t b0, uint32_t b1) {
    asm volatile(
        "mma.sync.aligned.m16n8k16.row.col.f32.bf16.bf16.f32 "
        "{%0,%1,%2,%3}, {%4,%5,%6,%7}, {%8,%9}, {%0,%1,%2,%3};"
        : "+f"(d[0]), "+f"(d[1]), "+f"(d[2]), "+f"(d[3])
        : "r"(a0), "r"(a1), "r"(a2), "r"(a3), "r"(b0), "r"(b1));
}
__device__ __forceinline__ void red_add_v2(float* ptr, float v0, float v1) {
    asm volatile("red.global.add.v2.f32 [%0], {%1,%2};"
        :: "l"(ptr), "f"(v0), "f"(v1) : "memory");
}

// ---------------- init: ln1 | zero | prepB (fused, 3 branches) --------------
__global__ __launch_bounds__(256) void init_kernel(
    const float* __restrict__ h, const float* __restrict__ g1,
    const float* __restrict__ b1, const float* __restrict__ We2)
{
    int b = blockIdx.x;
    int t = threadIdx.x;
    if (b < 1250) {
        int w = t >> 5, l = t & 31;
        int r = b * 8 + w;
        const float4 v = *(const float4*)&h[(size_t)r * CC + l * 4];
        float s  = v.x + v.y + v.z + v.w;
        float s2 = fmaf(v.x, v.x, fmaf(v.y, v.y, fmaf(v.z, v.z, v.w * v.w)));
#pragma unroll
        for (int o = 16; o; o >>= 1) {
            s  += __shfl_xor_sync(0xffffffffu, s,  o);
            s2 += __shfl_xor_sync(0xffffffffu, s2, o);
        }
        float mu   = s * (1.0f / CC);
        float var  = s2 * (1.0f / CC) - mu * mu;
        float rstd = rsqrtf(var + 1e-5f);
        float4 g  = *(const float4*)&g1[l * 4];
        float4 bb = *(const float4*)&b1[l * 4];
        float4 o;
        o.x = (v.x - mu) * rstd * g.x + bb.x;
        o.y = (v.y - mu) * rstd * g.y + bb.y;
        o.z = (v.z - mu) * rstd * g.z + bb.z;
        o.w = (v.w - mu) * rstd * g.w + bb.w;
        *(float4*)&g_hn[(size_t)r * CC + l * 4] = o;
    } else if (b < 11250) {
        int idx = (b - 1250) * 256 + t;          // exactly NN*HH
        g_msum[idx] = 0.0f;
        if (idx < NN) g_cnt[idx] = 0.0f;
    } else {
        int idx = (b - 11250) * 256 + t;         // 65536
        int n = idx >> 8, k = idx & 255;
        g_Bbf[n * HH + k] = __float2bfloat16(We2[(size_t)k * HH + n]);
    }
}

// ---------------- pre: PAB = hn @ We1 halves (FFMA, proven 41us) ------------
__global__ __launch_bounds__(256) void pre_kernel(const float* __restrict__ We1)
{
    __shared__ float s_in[CC][33];
    int t = threadIdx.x;
    int nb = blockIdx.x * 32;
    int half = blockIdx.y;
#pragma unroll
    for (int it = 0; it < 16; it++) {
        int idx = t + 256 * it;
        int e = idx >> 7, k = idx & 127;
        int n = nb + e; if (n >= NN) n = NN - 1;
        s_in[k][e] = g_hn[(size_t)n * CC + k];
    }
    __syncthreads();
    int j0 = (t & 63) * 4, e0 = (t >> 6) * 8;
    const float* Wp = We1 + (size_t)half * (128 * 256) + j0;
    float acc[8][4];
#pragma unroll
    for (int i = 0; i < 8; i++)
#pragma unroll
        for (int j = 0; j < 4; j++) acc[i][j] = 0.0f;
#pragma unroll 4
    for (int k = 0; k < CC; k++) {
        float4 w = *(const float4*)(Wp + (size_t)k * 256);
        float in[8];
#pragma unroll
        for (int i = 0; i < 8; i++) in[i] = s_in[k][e0 + i];
#pragma unroll
        for (int i = 0; i < 8; i++) {
            acc[i][0] += in[i] * w.x;
            acc[i][1] += in[i] * w.y;
            acc[i][2] += in[i] * w.z;
            acc[i][3] += in[i] * w.w;
        }
    }
#pragma unroll
    for (int i = 0; i < 8; i++) {
        int n = nb + e0 + i;
        if (n < NN) {
            float4 o; o.x = acc[i][0]; o.y = acc[i][1]; o.z = acc[i][2]; o.w = acc[i][3];
            *(float4*)&g_PAB[(size_t)n * 512 + half * 256 + j0] = o;
        }
    }
}

// ---------------- E1: layer-1 -> g_m1f (A-fragment layout), cc, counts ------
// Fragment layout (m16n8k16 A, verified in R6): for edge e, colpair cp:
//   kk = cp>>3, c8 = cp&7, lane = (e&7)*4 + (c8&3), j = (c8>>2)*2 + ((e&15)>>3)
//   uint32 idx = ((e>>4)*16 + kk)*128 + lane*4 + j
__global__ __launch_bounds__(256) void edge1_kernel(
    const float* __restrict__ x, const int* __restrict__ ei,
    const float* __restrict__ We1, const float* __restrict__ be1)
{
    __shared__ int   s_row[128], s_col[128];
    __shared__ float s_d[128];
    int t = threadIdx.x;
    int eb = blockIdx.x * 128;           // 2500 * 128 = 320000 exactly
    if (t < 128) {
        int e = eb + t;
        int r = ei[e], c = ei[EE + e];
        s_row[t] = r; s_col[t] = c;
        float dx = x[3 * r + 0] - x[3 * c + 0];
        float dy = x[3 * r + 1] - x[3 * c + 1];
        float dz = x[3 * r + 2] - x[3 * c + 2];
        float d = sqrtf(dx * dx + dy * dy + dz * dz);
        s_d[t] = d;
        float cc = (d <= 5.0f) ? 0.5f * (__cosf(d * 0.62831853071795864f) + 1.0f) : 0.0f;
        g_cc[e] = cc;
        atomicAdd(&g_cnt[c], 1.0f);
    }
    __syncthreads();
    int cp = t & 127;                    // colpair this thread owns
    int p2 = cp * 2;
    int eh = (t >> 7) * 64;
    int kk = cp >> 3, c8 = cp & 7;
    int laneb = c8 & 3, jb = (c8 >> 2) * 2;
    float wl0 = We1[65536 + p2], wl1 = We1[65536 + p2 + 1];
    float bb0 = be1[p2],         bb1 = be1[p2 + 1];
    // base for this block's fragments
    uint32_t* fb = g_m1f + ((size_t)(eb >> 4) * 16 + kk) * 128;
#pragma unroll 4
    for (int e = eh; e < eh + 64; e++) {
        int r = s_row[e], c = s_col[e];
        float2 pa = *(const float2*)&g_PAB[(size_t)r * 512 + p2];
        float2 pb = *(const float2*)&g_PAB[(size_t)c * 512 + 256 + p2];
        float dd = s_d[e];
        float u0 = silu_f(pa.x + pb.x + dd * wl0 + bb0);
        float u1 = silu_f(pa.y + pb.y + dd * wl1 + bb1);
        uint32_t pk;
        asm("cvt.rn.bf16x2.f32 %0, %1, %2;" : "=r"(pk) : "f"(u1), "f"(u0));
        int lane = (e & 7) * 4 + laneb;
        int j    = jb + ((e & 15) >> 3);
        fb[(size_t)(e >> 4) * (16 * 128) + lane * 4 + j] = pk;
    }
}

// ---------------- E2: GEMM (M=128 edges, N=64 quarter, K=256) + scatter -----
// grid (4, 2500). A fragments direct from g_m1f (LDG.128, no smem/ldsm).
// SMEM: B quarter only (~35 KB) -> 4 blocks/SM.
#define PB      528
#define OFF2_COL 0
#define OFF2_CC  512
#define OFF2_BE2 1024
#define B2_OFF   1536
#define E2_SMEM  (B2_OFF + 64 * PB)        // 35328 B

extern __shared__ char smx[];

__global__ __launch_bounds__(256, 4) void edge2_kernel(
    const int* __restrict__ ei, const float* __restrict__ be2)
{
    char* smem = smx;
    uint32_t smem_base = smem_u32(smem);
    int t = threadIdx.x;
    int wid = t >> 5, lid = t & 31;
    int q  = blockIdx.x;                 // N-quarter 0..3 (fastest -> A L2 reuse)
    int eb = blockIdx.y * 128;

    int*   s_col = (int*)(smem + OFF2_COL);
    float* s_cc  = (float*)(smem + OFF2_CC);
    float* s_be2 = (float*)(smem + OFF2_BE2);

    if (t < 128) {
        s_col[t] = ei[EE + eb + t];
        s_cc[t]  = g_cc[eb + t];
        if (t < 64) s_be2[t] = be2[q * 64 + t];
    }
    // B copy: rows [64q, 64q+64) x 512B (2048 int4)
    {
        const int4* src = (const int4*)g_Bbf + (size_t)q * 64 * 32;
        for (int i = t; i < 2048; i += 256)
            *(int4*)(smem + B2_OFF + (i >> 5) * PB + (i & 31) * 16) = src[i];
    }
    __syncthreads();

    // warp w: M-tile edges [eb + 16w, +16), full 64-col quarter
    int t16 = blockIdx.y * 8 + wid;      // global 16-edge tile index
    const uint4* aptr = (const uint4*)g_m1f + ((size_t)t16 * 16) * 32 + lid;
    uint32_t b_base4 = smem_base + B2_OFF
                     + (uint32_t)((lid & 7) + ((lid >> 4) & 1) * 8) * PB
                     + (uint32_t)((lid >> 3) & 1) * 16;

    float acc[8][4];
#pragma unroll
    for (int nt = 0; nt < 8; nt++)
#pragma unroll
        for (int j = 0; j < 4; j++) acc[nt][j] = 0.0f;

#pragma unroll 4
    for (int kk = 0; kk < 16; kk++) {
        uint4 af = aptr[kk * 32];        // a0..a3 fragments, one LDG.128
        uint32_t bk = b_base4 + kk * 32;
#pragma unroll
        for (int nt2 = 0; nt2 < 4; nt2++) {
            uint32_t b0, b1, b2, b3;
            ldsm_x4(b0, b1, b2, b3, bk + (uint32_t)nt2 * 16 * PB);
            mma_bf16(acc[2 * nt2],     af.x, af.y, af.z, af.w, b0, b1);
            mma_bf16(acc[2 * nt2 + 1], af.x, af.y, af.z, af.w, b2, b3);
        }
    }

    // epilogue: silu(+bias)*cc, vector red.v2 scatter
    int row0 = wid * 16 + (lid >> 2), row1 = row0 + 8;   // local edge in [0,128)
    float cc0 = s_cc[row0], cc1 = s_cc[row1];
    int   c0  = s_col[row0], c1 = s_col[row1];
    int   q2  = (lid & 3) * 2;
    int   nbase = q * 64;
#pragma unroll
    for (int nt = 0; nt < 8; nt++) {
        int nl = nt * 8 + q2;            // local col within quarter
        float bv0 = s_be2[nl], bv1 = s_be2[nl + 1];
        int gcol = nbase + nl;
        if (cc0 != 0.0f) {
            red_add_v2(&g_msum[(size_t)c0 * HH + gcol],
                       silu_f(acc[nt][0] + bv0) * cc0,
                       silu_f(acc[nt][1] + bv1) * cc0);
        }
        if (cc1 != 0.0f) {
            red_add_v2(&g_msum[(size_t)c1 * HH + gcol],
                       silu_f(acc[nt][2] + bv0) * cc1,
                       silu_f(acc[nt][3] + bv1) * cc1);
        }
    }
}

// ---------------- node1: t1 = silu([hn, m_aggr] @ Wn1 + bn1) ----------------
__global__ __launch_bounds__(256) void node1_kernel(
    const float* __restrict__ Wn1, const float* __restrict__ bn1)
{
    __shared__ float s_in[HH][33];
    int t = threadIdx.x;
    int nb = blockIdx.x * 32;
    int j0 = (t & 63) * 4, e0 = (t >> 6) * 8;
    float acc[8][4];
#pragma unroll
    for (int i = 0; i < 8; i++)
#pragma unroll
        for (int j = 0; j < 4; j++) acc[i][j] = 0.0f;
#pragma unroll
    for (int it = 0; it < 16; it++) {
        int idx = t + 256 * it;
        int e = idx >> 7, k = idx & 127;
        int n = nb + e; if (n >= NN) n = NN - 1;
        s_in[k][e] = g_hn[(size_t)n * CC + k];
    }
    __syncthreads();
    {
        const float* Wp = Wn1 + j0;
#pragma unroll 4
        for (int k = 0; k < 128; k++) {
            float4 w = *(const float4*)(Wp + (size_t)k * 256);
            float in[8];
#pragma unroll
            for (int i = 0; i < 8; i++) in[i] = s_in[k][e0 + i];
#pragma unroll
            for (int i = 0; i < 8; i++) {
                acc[i][0] += in[i] * w.x;
                acc[i][1] += in[i] * w.y;
                acc[i][2] += in[i] * w.z;
                acc[i][3] += in[i] * w.w;
            }
        }
    }
    __syncthreads();
    for (int it = 0; it < 32; it++) {
        int n = nb + it; if (n >= NN) n = NN - 1;
        float c = g_cnt[n];
        float inv = 1.0f / fmaxf(c, 1.0f);
        s_in[t][it] = g_msum[(size_t)n * HH + t] * inv;
    }
    __syncthreads();
    {
        const float* Wp = Wn1 + 128 * 256 + j0;
#pragma unroll 4
        for (int k = 0; k < HH; k++) {
            float4 w = *(const float4*)(Wp + (size_t)k * 256);
            float in[8];
#pragma unroll
            for (int i = 0; i < 8; i++) in[i] = s_in[k][e0 + i];
#pragma unroll
            for (int i = 0; i < 8; i++) {
                acc[i][0] += in[i] * w.x;
                acc[i][1] += in[i] * w.y;
                acc[i][2] += in[i] * w.z;
                acc[i][3] += in[i] * w.w;
            }
        }
    }
    float4 b = *(const float4*)(bn1 + j0);
#pragma unroll
    for (int i = 0; i < 8; i++) {
        int n = nb + e0 + i;
        if (n < NN) {
            float4 o;
            o.x = silu_f(acc[i][0] + b.x);
            o.y = silu_f(acc[i][1] + b.y);
            o.z = silu_f(acc[i][2] + b.z);
            o.w = silu_f(acc[i][3] + b.w);
            *(float4*)&g_t1[(size_t)n * HH + j0] = o;
        }
    }
}

// ---------------- node2 ----------------
__global__ __launch_bounds__(256) void node2_kernel(
    const float* __restrict__ h, const float* __restrict__ Wn2,
    const float* __restrict__ bn2, const float* __restrict__ g2,
    const float* __restrict__ beta2)
{
    __shared__ float s_in[HH][33];
    int t = threadIdx.x;
    int nb = blockIdx.x * 32;
    for (int it = 0; it < 32; it++) {
        int n = nb + it; if (n >= NN) n = NN - 1;
        s_in[t][it] = g_t1[(size_t)n * HH + t];
    }
    __syncthreads();
    int j0 = (t & 31) * 4, e0 = (t >> 5) * 4;
    float acc[4][4];
#pragma unroll
    for (int i = 0; i < 4; i++)
#pragma unroll
        for (int j = 0; j < 4; j++) acc[i][j] = 0.0f;
    const float* Wp = Wn2 + j0;
#pragma unroll 4
    for (int k = 0; k < HH; k++) {
        float4 w = *(const float4*)(Wp + (size_t)k * CC);
        float in[4];
#pragma unroll
        for (int i = 0; i < 4; i++) in[i] = s_in[k][e0 + i];
#pragma unroll
        for (int i = 0; i < 4; i++) {
            acc[i][0] += in[i] * w.x;
            acc[i][1] += in[i] * w.y;
            acc[i][2] += in[i] * w.z;
            acc[i][3] += in[i] * w.w;
        }
    }
    float4 b  = *(const float4*)(bn2 + j0);
    float4 gg = *(const float4*)(g2 + j0);
    float4 be = *(const float4*)(beta2 + j0);
#pragma unroll
    for (int i = 0; i < 4; i++) {
        int n = nb + e0 + i;
        bool valid = (n < NN);
        int nc = valid ? n : (NN - 1);
        float4 hv  = *(const float4*)&h[(size_t)nc * CC + j0];
        float4 hnv = *(const float4*)&g_hn[(size_t)nc * CC + j0];
        float v0 = hv.x + hnv.x + acc[i][0] + b.x;
        float v1 = hv.y + hnv.y + acc[i][1] + b.y;
        float v2 = hv.z + hnv.z + acc[i][2] + b.z;
        float v3 = hv.w + hnv.w + acc[i][3] + b.w;
        float s  = v0 + v1 + v2 + v3;
        float s2 = fmaf(v0, v0, fmaf(v1, v1, fmaf(v2, v2, v3 * v3)));
#pragma unroll
        for (int o = 16; o; o >>= 1) {
            s  += __shfl_xor_sync(0xffffffffu, s,  o);
            s2 += __shfl_xor_sync(0xffffffffu, s2, o);
        }
        float mu   = s * (1.0f / CC);
        float var  = s2 * (1.0f / CC) - mu * mu;
        float rstd = rsqrtf(var + 1e-5f);
        if (valid) {
            float4 h1v; h1v.x = v0; h1v.y = v1; h1v.z = v2; h1v.w = v3;
            *(float4*)&g_h1[(size_t)n * CC + j0] = h1v;
            float4 o;
            o.x = (v0 - mu) * rstd * gg.x + be.x;
            o.y = (v1 - mu) * rstd * gg.y + be.y;
            o.z = (v2 - mu) * rstd * gg.z + be.z;
            o.w = (v3 - mu) * rstd * gg.w + be.w;
            *(float4*)&g_h2n[(size_t)n * CC + j0] = o;
        }
    }
}

// ---------------- node3 ----------------
__global__ __launch_bounds__(256) void node3_kernel(
    const float* __restrict__ Wm1, const float* __restrict__ bm1)
{
    __shared__ float s_in[CC][33];
    int t = threadIdx.x;
    int nb = blockIdx.x * 32;
#pragma unroll
    for (int it = 0; it < 16; it++) {
        int idx = t + 256 * it;
        int e = idx >> 7, k = idx & 127;
        int n = nb + e; if (n >= NN) n = NN - 1;
        s_in[k][e] = g_h2n[(size_t)n * CC + k];
    }
    __syncthreads();
    int j0 = (t & 63) * 4, e0 = (t >> 6) * 8;
    float acc[8][4];
#pragma unroll
    for (int i = 0; i < 8; i++)
#pragma unroll
        for (int j = 0; j < 4; j++) acc[i][j] = 0.0f;
    const float* Wp = Wm1 + j0;
#pragma unroll 4
    for (int k = 0; k < CC; k++) {
        float4 w = *(const float4*)(Wp + (size_t)k * HH);
        float in[8];
#pragma unroll
        for (int i = 0; i < 8; i++) in[i] = s_in[k][e0 + i];
#pragma unroll
        for (int i = 0; i < 8; i++) {
            acc[i][0] += in[i] * w.x;
            acc[i][1] += in[i] * w.y;
            acc[i][2] += in[i] * w.z;
            acc[i][3] += in[i] * w.w;
        }
    }
    float4 b = *(const float4*)(bm1 + j0);
#pragma unroll
    for (int i = 0; i < 8; i++) {
        int n = nb + e0 + i;
        if (n < NN) {
            float4 o;
            o.x = silu_f(acc[i][0] + b.x);
            o.y = silu_f(acc[i][1] + b.y);
            o.z = silu_f(acc[i][2] + b.z);
            o.w = silu_f(acc[i][3] + b.w);
            *(float4*)&g_t2[(size_t)n * HH + j0] = o;
        }
    }
}

// ---------------- node4 ----------------
__global__ __launch_bounds__(256) void node4_kernel(
    const float* __restrict__ Wm2, const float* __restrict__ bm2,
    float* __restrict__ out)
{
    __shared__ float s_in[HH][33];
    int t = threadIdx.x;
    int nb = blockIdx.x * 32;
    for (int it = 0; it < 32; it++) {
        int n = nb + it; if (n >= NN) n = NN - 1;
        s_in[t][it] = g_t2[(size_t)n * HH + t];
    }
    __syncthreads();
    int j0 = (t & 31) * 4, e0 = (t >> 5) * 4;
    float acc[4][4];
#pragma unroll
    for (int i = 0; i < 4; i++)
#pragma unroll
        for (int j = 0; j < 4; j++) acc[i][j] = 0.0f;
    const float* Wp = Wm2 + j0;
#pragma unroll 4
    for (int k = 0; k < HH; k++) {
        float4 w = *(const float4*)(Wp + (size_t)k * CC);
        float in[4];
#pragma unroll
        for (int i = 0; i < 4; i++) in[i] = s_in[k][e0 + i];
#pragma unroll
        for (int i = 0; i < 4; i++) {
            acc[i][0] += in[i] * w.x;
            acc[i][1] += in[i] * w.y;
            acc[i][2] += in[i] * w.z;
            acc[i][3] += in[i] * w.w;
        }
    }
    float4 b = *(const float4*)(bm2 + j0);
#pragma unroll
    for (int i = 0; i < 4; i++) {
        int n = nb + e0 + i;
        if (n < NN) {
            float4 h1v = *(const float4*)&g_h1[(size_t)n * CC + j0];
            float4 o;
            o.x = h1v.x + acc[i][0] + b.x;
            o.y = h1v.y + acc[i][1] + b.y;
            o.z = h1v.z + acc[i][2] + b.z;
            o.w = h1v.w + acc[i][3] + b.w;
            *(float4*)&out[(size_t)n * CC + j0] = o;
        }
    }
}

// ---------------- launch ----------------
extern "C" void kernel_launch(void* const* d_in, const int* in_sizes, int n_in,
                              void* d_out, int out_size)
{
    const float* x     = (const float*)d_in[0];
    const float* h     = (const float*)d_in[1];
    const int*   ei    = (const int*)d_in[2];
    const float* We1   = (const float*)d_in[3];
    const float* be1   = (const float*)d_in[4];
    const float* We2   = (const float*)d_in[5];
    const float* be2   = (const float*)d_in[6];
    const float* Wn1   = (const float*)d_in[7];
    const float* bn1   = (const float*)d_in[8];
    const float* Wn2   = (const float*)d_in[9];
    const float* bn2   = (const float*)d_in[10];
    const float* Wm1   = (const float*)d_in[11];
    const float* bm1   = (const float*)d_in[12];
    const float* Wm2   = (const float*)d_in[13];
    const float* bm2   = (const float*)d_in[14];
    const float* g1    = (const float*)d_in[15];
    const float* beta1 = (const float*)d_in[16];
    const float* g2    = (const float*)d_in[17];
    const float* beta2 = (const float*)d_in[18];
    float* out = (float*)d_out;

    static int smem_set = 0;
    if (!smem_set) {
        cudaFuncSetAttribute(edge2_kernel,
                             cudaFuncAttributeMaxDynamicSharedMemorySize, E2_SMEM);
        smem_set = 1;
    }

    int nblk = (NN + 31) / 32;  // 313

    init_kernel<<<11506, 256>>>(h, g1, beta1, We2);
    pre_kernel<<<dim3(nblk, 2), 256>>>(We1);
    edge1_kernel<<<EE / 128, 256>>>(x, ei, We1, be1);
    edge2_kernel<<<dim3(4, EE / 128), 256, E2_SMEM>>>(ei, be2);
    node1_kernel<<<nblk, 256>>>(Wn1, bn1);
    node2_kernel<<<nblk, 256>>>(h, Wn2, bn2, g2, beta2);
    node3_kernel<<<nblk, 256>>>(Wm1, bm1);
    node4_kernel<<<nblk, 256>>>(Wm2, bm2, out);
}

// round 14
// speedup vs baseline: 1.4494x; 1.4494x over previous
#include <cuda_runtime.h>
#include <cuda_bf16.h>
#include <math.h>
#include <stdint.h>

#define NN 10000
#define CC 128
#define HH 256
#define EE 320000

// ---------------- scratch (device globals; no allocation allowed) ------------
__device__ float g_hn  [NN * CC];    // LN1(h)
__device__ float g_PAB [NN * 512];   // [ hn@We1[0:128] | hn@We1[128:256] ]
__device__ float g_msum[NN * HH];    // segment sums (atomic target)
__device__ float g_cnt [NN];         // segment counts
__device__ float g_t1  [NN * HH];
__device__ float g_h1  [NN * CC];
__device__ float g_h2n [NN * CC];
__device__ float g_t2  [NN * HH];
__device__ __nv_bfloat16 g_Bbf[HH * HH];      // Bbf[n][k] = bf16(We2[k][n])
__device__ uint32_t g_m1f[(size_t)EE * 128];  // m1 in mma A-fragment layout (bf16x2)
__device__ float g_cc  [EE];                  // cutoff per edge

__device__ __forceinline__ float silu_f(float v) {
    return v / (1.0f + __expf(-v));
}

__device__ __forceinline__ uint32_t smem_u32(const void* p) {
    uint32_t a;
    asm("{ .reg .u64 t; cvta.to.shared.u64 t, %1; cvt.u32.u64 %0, t; }"
        : "=r"(a) : "l"(p));
    return a;
}
__device__ __forceinline__ void ldsm_x4(uint32_t& a0, uint32_t& a1,
                                        uint32_t& a2, uint32_t& a3, uint32_t addr) {
    asm volatile("ldmatrix.sync.aligned.m8n8.x4.shared.b16 {%0,%1,%2,%3}, [%4];"
        : "=r"(a0), "=r"(a1), "=r"(a2), "=r"(a3) : "r"(addr));
}
__device__ __forceinline__ void mma_bf16(float* d, uint32_t a0, uint32_t a1,
                                         uint32_t a2, uint32_t a3,
                                         uint32_t b0, uint32_t b1) {
    asm volatile(
        "mma.sync.aligned.m16n8k16.row.col.f32.bf16.bf16.f32 "
        "{%0,%1,%2,%3}, {%4,%5,%6,%7}, {%8,%9}, {%0,%1,%2,%3};"
        : "+f"(d[0]), "+f"(d[1]), "+f"(d[2]), "+f"(d[3])
        : "r"(a0), "r"(a1), "r"(a2), "r"(a3), "r"(b0), "r"(b1));
}
__device__ __forceinline__ void red_add_v2(float* ptr, float v0, float v1) {
    asm volatile("red.global.add.v2.f32 [%0], {%1,%2};"
        :: "l"(ptr), "f"(v0), "f"(v1) : "memory");
}

// ---------------- init: ln1 | zero | prepB (fused, 3 branches) --------------
__global__ __launch_bounds__(256) void init_kernel(
    const float* __restrict__ h, const float* __restrict__ g1,
    const float* __restrict__ b1, const float* __restrict__ We2)
{
    int b = blockIdx.x;
    int t = threadIdx.x;
    if (b < 1250) {
        int w = t >> 5, l = t & 31;
        int r = b * 8 + w;
        const float4 v = *(const float4*)&h[(size_t)r * CC + l * 4];
        float s  = v.x + v.y + v.z + v.w;
        float s2 = fmaf(v.x, v.x, fmaf(v.y, v.y, fmaf(v.z, v.z, v.w * v.w)));
#pragma unroll
        for (int o = 16; o; o >>= 1) {
            s  += __shfl_xor_sync(0xffffffffu, s,  o);
            s2 += __shfl_xor_sync(0xffffffffu, s2, o);
        }
        float mu   = s * (1.0f / CC);
        float var  = s2 * (1.0f / CC) - mu * mu;
        float rstd = rsqrtf(var + 1e-5f);
        float4 g  = *(const float4*)&g1[l * 4];
        float4 bb = *(const float4*)&b1[l * 4];
        float4 o;
        o.x = (v.x - mu) * rstd * g.x + bb.x;
        o.y = (v.y - mu) * rstd * g.y + bb.y;
        o.z = (v.z - mu) * rstd * g.z + bb.z;
        o.w = (v.w - mu) * rstd * g.w + bb.w;
        *(float4*)&g_hn[(size_t)r * CC + l * 4] = o;
    } else if (b < 11250) {
        int idx = (b - 1250) * 256 + t;          // exactly NN*HH
        g_msum[idx] = 0.0f;
        if (idx < NN) g_cnt[idx] = 0.0f;
    } else {
        int idx = (b - 11250) * 256 + t;         // 65536
        int n = idx >> 8, k = idx & 255;
        g_Bbf[n * HH + k] = __float2bfloat16(We2[(size_t)k * HH + n]);
    }
}

// ---------------- pre: PAB = hn @ We1 halves (FFMA, proven 41us) ------------
__global__ __launch_bounds__(256) void pre_kernel(const float* __restrict__ We1)
{
    __shared__ float s_in[CC][33];
    int t = threadIdx.x;
    int nb = blockIdx.x * 32;
    int half = blockIdx.y;
#pragma unroll
    for (int it = 0; it < 16; it++) {
        int idx = t + 256 * it;
        int e = idx >> 7, k = idx & 127;
        int n = nb + e; if (n >= NN) n = NN - 1;
        s_in[k][e] = g_hn[(size_t)n * CC + k];
    }
    __syncthreads();
    int j0 = (t & 63) * 4, e0 = (t >> 6) * 8;
    const float* Wp = We1 + (size_t)half * (128 * 256) + j0;
    float acc[8][4];
#pragma unroll
    for (int i = 0; i < 8; i++)
#pragma unroll
        for (int j = 0; j < 4; j++) acc[i][j] = 0.0f;
#pragma unroll 4
    for (int k = 0; k < CC; k++) {
        float4 w = *(const float4*)(Wp + (size_t)k * 256);
        float in[8];
#pragma unroll
        for (int i = 0; i < 8; i++) in[i] = s_in[k][e0 + i];
#pragma unroll
        for (int i = 0; i < 8; i++) {
            acc[i][0] += in[i] * w.x;
            acc[i][1] += in[i] * w.y;
            acc[i][2] += in[i] * w.z;
            acc[i][3] += in[i] * w.w;
        }
    }
#pragma unroll
    for (int i = 0; i < 8; i++) {
        int n = nb + e0 + i;
        if (n < NN) {
            float4 o; o.x = acc[i][0]; o.y = acc[i][1]; o.z = acc[i][2]; o.w = acc[i][3];
            *(float4*)&g_PAB[(size_t)n * 512 + half * 256 + j0] = o;
        }
    }
}

// ---------------- E1: layer-1 -> SMEM stage -> g_m1f (coalesced) ------------
// Compute with R11 mapping (coalesced PAB loads), stage in s_m1 (pitch 132),
// then pack 4 words per thread into STG.128 in fragment layout.
// Forward fragment map (proven): e,cp -> kk=cp>>3, c8=cp&7,
//   lane=(e&7)*4+(c8&3), j=(c8>>2)*2+((e&15)>>3)
// Inverse (used in write-out): e = tile*16+((j&1)<<3)+(lane>>2),
//   cp = (kk<<3)+((j>>1)<<2)+(lane&3)
#define E1PITCH 132
#define E1_SMEM (E1PITCH * 128 * 4)        // 67584 B

extern __shared__ char smx[];

__global__ __launch_bounds__(256) void edge1_kernel(
    const float* __restrict__ x, const int* __restrict__ ei,
    const float* __restrict__ We1, const float* __restrict__ be1)
{
    uint32_t* s_m1 = (uint32_t*)smx;       // [128 edges][pitch 132]
    __shared__ int   s_row[128], s_col[128];
    __shared__ float s_d[128];
    int t = threadIdx.x;
    int eb = blockIdx.x * 128;             // 2500 * 128 = 320000 exactly
    if (t < 128) {
        int e = eb + t;
        int r = ei[e], c = ei[EE + e];
        s_row[t] = r; s_col[t] = c;
        float dx = x[3 * r + 0] - x[3 * c + 0];
        float dy = x[3 * r + 1] - x[3 * c + 1];
        float dz = x[3 * r + 2] - x[3 * c + 2];
        float d = sqrtf(dx * dx + dy * dy + dz * dz);
        s_d[t] = d;
        float cc = (d <= 5.0f) ? 0.5f * (__cosf(d * 0.62831853071795864f) + 1.0f) : 0.0f;
        g_cc[e] = cc;
        atomicAdd(&g_cnt[c], 1.0f);
    }
    __syncthreads();
    // ---- compute phase: thread owns colpair cp for 64 edges ----
    {
        int cp = t & 127;
        int p2 = cp * 2;
        int eh = (t >> 7) * 64;
        float wl0 = We1[65536 + p2], wl1 = We1[65536 + p2 + 1];
        float bb0 = be1[p2],         bb1 = be1[p2 + 1];
#pragma unroll 4
        for (int e = eh; e < eh + 64; e++) {
            int r = s_row[e], c = s_col[e];
            float2 pa = *(const float2*)&g_PAB[(size_t)r * 512 + p2];
            float2 pb = *(const float2*)&g_PAB[(size_t)c * 512 + 256 + p2];
            float dd = s_d[e];
            float u0 = silu_f(pa.x + pb.x + dd * wl0 + bb0);
            float u1 = silu_f(pa.y + pb.y + dd * wl1 + bb1);
            uint32_t pk;
            asm("cvt.rn.bf16x2.f32 %0, %1, %2;" : "=r"(pk) : "f"(u1), "f"(u0));
            s_m1[e * E1PITCH + cp] = pk;   // same e across warp, cp consecutive
        }
    }
    __syncthreads();
    // ---- write-out phase: fragment layout, STG.128 coalesced ----
    {
        int lane = t & 31;
        uint4* gout = (uint4*)g_m1f;
        size_t gt16base = (size_t)(blockIdx.x * 8) * 16;   // tile base *16
#pragma unroll 4
        for (int i = 0; i < 16; i++) {
            int u4 = t + 256 * i;          // [0, 4096)
            int tilekk = u4 >> 5;          // tile*16 + kk
            int tile = tilekk >> 4, kk = tilekk & 15;
            uint32_t v[4];
#pragma unroll
            for (int j = 0; j < 4; j++) {
                int e  = tile * 16 + ((j & 1) << 3) + (lane >> 2);
                int cp = (kk << 3) + ((j >> 1) << 2) + (lane & 3);
                v[j] = s_m1[e * E1PITCH + cp];
            }
            uint4 o; o.x = v[0]; o.y = v[1]; o.z = v[2]; o.w = v[3];
            gout[(gt16base + tilekk) * 32 + lane] = o;
        }
    }
}

// ---------------- E2: GEMM (M=128 edges, N=64 quarter, K=256) + scatter -----
// grid (4, 2500). A fragments direct from g_m1f (LDG.128, no smem/ldsm).
#define PB      528
#define OFF2_COL 0
#define OFF2_CC  512
#define OFF2_BE2 1024
#define B2_OFF   1536
#define E2_SMEM  (B2_OFF + 64 * PB)        // 35328 B

__global__ __launch_bounds__(256, 4) void edge2_kernel(
    const int* __restrict__ ei, const float* __restrict__ be2)
{
    char* smem = smx;
    uint32_t smem_base = smem_u32(smem);
    int t = threadIdx.x;
    int wid = t >> 5, lid = t & 31;
    int q  = blockIdx.x;                 // N-quarter 0..3 (fastest -> A L2 reuse)
    int eb = blockIdx.y * 128;

    int*   s_col = (int*)(smem + OFF2_COL);
    float* s_cc  = (float*)(smem + OFF2_CC);
    float* s_be2 = (float*)(smem + OFF2_BE2);

    if (t < 128) {
        s_col[t] = ei[EE + eb + t];
        s_cc[t]  = g_cc[eb + t];
        if (t < 64) s_be2[t] = be2[q * 64 + t];
    }
    // B copy: rows [64q, 64q+64) x 512B (2048 int4)
    {
        const int4* src = (const int4*)g_Bbf + (size_t)q * 64 * 32;
        for (int i = t; i < 2048; i += 256)
            *(int4*)(smem + B2_OFF + (i >> 5) * PB + (i & 31) * 16) = src[i];
    }
    __syncthreads();

    // warp w: M-tile edges [eb + 16w, +16), full 64-col quarter
    int t16 = blockIdx.y * 8 + wid;      // global 16-edge tile index
    const uint4* aptr = (const uint4*)g_m1f + ((size_t)t16 * 16) * 32 + lid;
    uint32_t b_base4 = smem_base + B2_OFF
                     + (uint32_t)((lid & 7) + ((lid >> 4) & 1) * 8) * PB
                     + (uint32_t)((lid >> 3) & 1) * 16;

    float acc[8][4];
#pragma unroll
    for (int nt = 0; nt < 8; nt++)
#pragma unroll
        for (int j = 0; j < 4; j++) acc[nt][j] = 0.0f;

#pragma unroll 4
    for (int kk = 0; kk < 16; kk++) {
        uint4 af = aptr[kk * 32];        // a0..a3 fragments, one LDG.128
        uint32_t bk = b_base4 + kk * 32;
#pragma unroll
        for (int nt2 = 0; nt2 < 4; nt2++) {
            uint32_t b0, b1, b2, b3;
            ldsm_x4(b0, b1, b2, b3, bk + (uint32_t)nt2 * 16 * PB);
            mma_bf16(acc[2 * nt2],     af.x, af.y, af.z, af.w, b0, b1);
            mma_bf16(acc[2 * nt2 + 1], af.x, af.y, af.z, af.w, b2, b3);
        }
    }

    // epilogue: silu(+bias)*cc, vector red.v2 scatter
    int row0 = wid * 16 + (lid >> 2), row1 = row0 + 8;   // local edge in [0,128)
    float cc0 = s_cc[row0], cc1 = s_cc[row1];
    int   c0  = s_col[row0], c1 = s_col[row1];
    int   q2  = (lid & 3) * 2;
    int   nbase = q * 64;
#pragma unroll
    for (int nt = 0; nt < 8; nt++) {
        int nl = nt * 8 + q2;            // local col within quarter
        float bv0 = s_be2[nl], bv1 = s_be2[nl + 1];
        int gcol = nbase + nl;
        if (cc0 != 0.0f) {
            red_add_v2(&g_msum[(size_t)c0 * HH + gcol],
                       silu_f(acc[nt][0] + bv0) * cc0,
                       silu_f(acc[nt][1] + bv1) * cc0);
        }
        if (cc1 != 0.0f) {
            red_add_v2(&g_msum[(size_t)c1 * HH + gcol],
                       silu_f(acc[nt][2] + bv0) * cc1,
                       silu_f(acc[nt][3] + bv1) * cc1);
        }
    }
}

// ---------------- node1: t1 = silu([hn, m_aggr] @ Wn1 + bn1) ----------------
__global__ __launch_bounds__(256) void node1_kernel(
    const float* __restrict__ Wn1, const float* __restrict__ bn1)
{
    __shared__ float s_in[HH][33];
    int t = threadIdx.x;
    int nb = blockIdx.x * 32;
    int j0 = (t & 63) * 4, e0 = (t >> 6) * 8;
    float acc[8][4];
#pragma unroll
    for (int i = 0; i < 8; i++)
#pragma unroll
        for (int j = 0; j < 4; j++) acc[i][j] = 0.0f;
#pragma unroll
    for (int it = 0; it < 16; it++) {
        int idx = t + 256 * it;
        int e = idx >> 7, k = idx & 127;
        int n = nb + e; if (n >= NN) n = NN - 1;
        s_in[k][e] = g_hn[(size_t)n * CC + k];
    }
    __syncthreads();
    {
        const float* Wp = Wn1 + j0;
#pragma unroll 4
        for (int k = 0; k < 128; k++) {
            float4 w = *(const float4*)(Wp + (size_t)k * 256);
            float in[8];
#pragma unroll
            for (int i = 0; i < 8; i++) in[i] = s_in[k][e0 + i];
#pragma unroll
            for (int i = 0; i < 8; i++) {
                acc[i][0] += in[i] * w.x;
                acc[i][1] += in[i] * w.y;
                acc[i][2] += in[i] * w.z;
                acc[i][3] += in[i] * w.w;
            }
        }
    }
    __syncthreads();
    for (int it = 0; it < 32; it++) {
        int n = nb + it; if (n >= NN) n = NN - 1;
        float c = g_cnt[n];
        float inv = 1.0f / fmaxf(c, 1.0f);
        s_in[t][it] = g_msum[(size_t)n * HH + t] * inv;
    }
    __syncthreads();
    {
        const float* Wp = Wn1 + 128 * 256 + j0;
#pragma unroll 4
        for (int k = 0; k < HH; k++) {
            float4 w = *(const float4*)(Wp + (size_t)k * 256);
            float in[8];
#pragma unroll
            for (int i = 0; i < 8; i++) in[i] = s_in[k][e0 + i];
#pragma unroll
            for (int i = 0; i < 8; i++) {
                acc[i][0] += in[i] * w.x;
                acc[i][1] += in[i] * w.y;
                acc[i][2] += in[i] * w.z;
                acc[i][3] += in[i] * w.w;
            }
        }
    }
    float4 b = *(const float4*)(bn1 + j0);
#pragma unroll
    for (int i = 0; i < 8; i++) {
        int n = nb + e0 + i;
        if (n < NN) {
            float4 o;
            o.x = silu_f(acc[i][0] + b.x);
            o.y = silu_f(acc[i][1] + b.y);
            o.z = silu_f(acc[i][2] + b.z);
            o.w = silu_f(acc[i][3] + b.w);
            *(float4*)&g_t1[(size_t)n * HH + j0] = o;
        }
    }
}

// ---------------- node2 ----------------
__global__ __launch_bounds__(256) void node2_kernel(
    const float* __restrict__ h, const float* __restrict__ Wn2,
    const float* __restrict__ bn2, const float* __restrict__ g2,
    const float* __restrict__ beta2)
{
    __shared__ float s_in[HH][33];
    int t = threadIdx.x;
    int nb = blockIdx.x * 32;
    for (int it = 0; it < 32; it++) {
        int n = nb + it; if (n >= NN) n = NN - 1;
        s_in[t][it] = g_t1[(size_t)n * HH + t];
    }
    __syncthreads();
    int j0 = (t & 31) * 4, e0 = (t >> 5) * 4;
    float acc[4][4];
#pragma unroll
    for (int i = 0; i < 4; i++)
#pragma unroll
        for (int j = 0; j < 4; j++) acc[i][j] = 0.0f;
    const float* Wp = Wn2 + j0;
#pragma unroll 4
    for (int k = 0; k < HH; k++) {
        float4 w = *(const float4*)(Wp + (size_t)k * CC);
        float in[4];
#pragma unroll
        for (int i = 0; i < 4; i++) in[i] = s_in[k][e0 + i];
#pragma unroll
        for (int i = 0; i < 4; i++) {
            acc[i][0] += in[i] * w.x;
            acc[i][1] += in[i] * w.y;
            acc[i][2] += in[i] * w.z;
            acc[i][3] += in[i] * w.w;
        }
    }
    float4 b  = *(const float4*)(bn2 + j0);
    float4 gg = *(const float4*)(g2 + j0);
    float4 be = *(const float4*)(beta2 + j0);
#pragma unroll
    for (int i = 0; i < 4; i++) {
        int n = nb + e0 + i;
        bool valid = (n < NN);
        int nc = valid ? n : (NN - 1);
        float4 hv  = *(const float4*)&h[(size_t)nc * CC + j0];
        float4 hnv = *(const float4*)&g_hn[(size_t)nc * CC + j0];
        float v0 = hv.x + hnv.x + acc[i][0] + b.x;
        float v1 = hv.y + hnv.y + acc[i][1] + b.y;
        float v2 = hv.z + hnv.z + acc[i][2] + b.z;
        float v3 = hv.w + hnv.w + acc[i][3] + b.w;
        float s  = v0 + v1 + v2 + v3;
        float s2 = fmaf(v0, v0, fmaf(v1, v1, fmaf(v2, v2, v3 * v3)));
#pragma unroll
        for (int o = 16; o; o >>= 1) {
            s  += __shfl_xor_sync(0xffffffffu, s,  o);
            s2 += __shfl_xor_sync(0xffffffffu, s2, o);
        }
        float mu   = s * (1.0f / CC);
        float var  = s2 * (1.0f / CC) - mu * mu;
        float rstd = rsqrtf(var + 1e-5f);
        if (valid) {
            float4 h1v; h1v.x = v0; h1v.y = v1; h1v.z = v2; h1v.w = v3;
            *(float4*)&g_h1[(size_t)n * CC + j0] = h1v;
            float4 o;
            o.x = (v0 - mu) * rstd * gg.x + be.x;
            o.y = (v1 - mu) * rstd * gg.y + be.y;
            o.z = (v2 - mu) * rstd * gg.z + be.z;
            o.w = (v3 - mu) * rstd * gg.w + be.w;
            *(float4*)&g_h2n[(size_t)n * CC + j0] = o;
        }
    }
}

// ---------------- node3 ----------------
__global__ __launch_bounds__(256) void node3_kernel(
    const float* __restrict__ Wm1, const float* __restrict__ bm1)
{
    __shared__ float s_in[CC][33];
    int t = threadIdx.x;
    int nb = blockIdx.x * 32;
#pragma unroll
    for (int it = 0; it < 16; it++) {
        int idx = t + 256 * it;
        int e = idx >> 7, k = idx & 127;
        int n = nb + e; if (n >= NN) n = NN - 1;
        s_in[k][e] = g_h2n[(size_t)n * CC + k];
    }
    __syncthreads();
    int j0 = (t & 63) * 4, e0 = (t >> 6) * 8;
    float acc[8][4];
#pragma unroll
    for (int i = 0; i < 8; i++)
#pragma unroll
        for (int j = 0; j < 4; j++) acc[i][j] = 0.0f;
    const float* Wp = Wm1 + j0;
#pragma unroll 4
    for (int k = 0; k < CC; k++) {
        float4 w = *(const float4*)(Wp + (size_t)k * HH);
        float in[8];
#pragma unroll
        for (int i = 0; i < 8; i++) in[i] = s_in[k][e0 + i];
#pragma unroll
        for (int i = 0; i < 8; i++) {
            acc[i][0] += in[i] * w.x;
            acc[i][1] += in[i] * w.y;
            acc[i][2] += in[i] * w.z;
            acc[i][3] += in[i] * w.w;
        }
    }
    float4 b = *(const float4*)(bm1 + j0);
#pragma unroll
    for (int i = 0; i < 8; i++) {
        int n = nb + e0 + i;
        if (n < NN) {
            float4 o;
            o.x = silu_f(acc[i][0] + b.x);
            o.y = silu_f(acc[i][1] + b.y);
            o.z = silu_f(acc[i][2] + b.z);
            o.w = silu_f(acc[i][3] + b.w);
            *(float4*)&g_t2[(size_t)n * HH + j0] = o;
        }
    }
}

// ---------------- node4 ----------------
__global__ __launch_bounds__(256) void node4_kernel(
    const float* __restrict__ Wm2, const float* __restrict__ bm2,
    float* __restrict__ out)
{
    __shared__ float s_in[HH][33];
    int t = threadIdx.x;
    int nb = blockIdx.x * 32;
    for (int it = 0; it < 32; it++) {
        int n = nb + it; if (n >= NN) n = NN - 1;
        s_in[t][it] = g_t2[(size_t)n * HH + t];
    }
    __syncthreads();
    int j0 = (t & 31) * 4, e0 = (t >> 5) * 4;
    float acc[4][4];
#pragma unroll
    for (int i = 0; i < 4; i++)
#pragma unroll
        for (int j = 0; j < 4; j++) acc[i][j] = 0.0f;
    const float* Wp = Wm2 + j0;
#pragma unroll 4
    for (int k = 0; k < HH; k++) {
        float4 w = *(const float4*)(Wp + (size_t)k * CC);
        float in[4];
#pragma unroll
        for (int i = 0; i < 4; i++) in[i] = s_in[k][e0 + i];
#pragma unroll
        for (int i = 0; i < 4; i++) {
            acc[i][0] += in[i] * w.x;
            acc[i][1] += in[i] * w.y;
            acc[i][2] += in[i] * w.z;
            acc[i][3] += in[i] * w.w;
        }
    }
    float4 b = *(const float4*)(bm2 + j0);
#pragma unroll
    for (int i = 0; i < 4; i++) {
        int n = nb + e0 + i;
        if (n < NN) {
            float4 h1v = *(const float4*)&g_h1[(size_t)n * CC + j0];
            float4 o;
            o.x = h1v.x + acc[i][0] + b.x;
            o.y = h1v.y + acc[i][1] + b.y;
            o.z = h1v.z + acc[i][2] + b.z;
            o.w = h1v.w + acc[i][3] + b.w;
            *(float4*)&out[(size_t)n * CC + j0] = o;
        }
    }
}

// ---------------- launch ----------------
extern "C" void kernel_launch(void* const* d_in, const int* in_sizes, int n_in,
                              void* d_out, int out_size)
{
    const float* x     = (const float*)d_in[0];
    const float* h     = (const float*)d_in[1];
    const int*   ei    = (const int*)d_in[2];
    const float* We1   = (const float*)d_in[3];
    const float* be1   = (const float*)d_in[4];
    const float* We2   = (const float*)d_in[5];
    const float* be2   = (const float*)d_in[6];
    const float* Wn1   = (const float*)d_in[7];
    const float* bn1   = (const float*)d_in[8];
    const float* Wn2   = (const float*)d_in[9];
    const float* bn2   = (const float*)d_in[10];
    const float* Wm1   = (const float*)d_in[11];
    const float* bm1   = (const float*)d_in[12];
    const float* Wm2   = (const float*)d_in[13];
    const float* bm2   = (const float*)d_in[14];
    const float* g1    = (const float*)d_in[15];
    const float* beta1 = (const float*)d_in[16];
    const float* g2    = (const float*)d_in[17];
    const float* beta2 = (const float*)d_in[18];
    float* out = (float*)d_out;

    static int smem_set = 0;
    if (!smem_set) {
        cudaFuncSetAttribute(edge1_kernel,
                             cudaFuncAttributeMaxDynamicSharedMemorySize, E1_SMEM);
        cudaFuncSetAttribute(edge2_kernel,
                             cudaFuncAttributeMaxDynamicSharedMemorySize, E2_SMEM);
        smem_set = 1;
    }

    int nblk = (NN + 31) / 32;  // 313

    init_kernel<<<11506, 256>>>(h, g1, beta1, We2);
    pre_kernel<<<dim3(nblk, 2), 256>>>(We1);
    edge1_kernel<<<EE / 128, 256, E1_SMEM>>>(x, ei, We1, be1);
    edge2_kernel<<<dim3(4, EE / 128), 256, E2_SMEM>>>(ei, be2);
    node1_kernel<<<nblk, 256>>>(Wn1, bn1);
    node2_kernel<<<nblk, 256>>>(h, Wn2, bn2, g2, beta2);
    node3_kernel<<<nblk, 256>>>(Wm1, bm1);
    node4_kernel<<<nblk, 256>>>(Wm2, bm2, out);
}

// round 15
// speedup vs baseline: 1.6663x; 1.1496x over previous
#include <cuda_runtime.h>
#include <cuda_bf16.h>
#include <math.h>
#include <stdint.h>

#define NN 10000
#define CC 128
#define HH 256
#define EE 320000

// ---------------- scratch (device globals; no allocation allowed) ------------
__device__ float g_hn  [NN * CC];    // LN1(h)
__device__ float g_PAB [NN * 512];   // [ hn@We1[0:128] | hn@We1[128:256] ]
__device__ float g_msum[NN * HH];    // segment sums (atomic target)
__device__ float g_cnt [NN];         // segment counts
__device__ float g_t1  [NN * HH];
__device__ float g_h1  [NN * CC];
__device__ float g_h2n [NN * CC];
__device__ float g_t2  [NN * HH];
__device__ __nv_bfloat16 g_Bbf[HH * HH];      // Bbf[n][k] = bf16(We2[k][n])

__device__ __forceinline__ float silu_f(float v) {
    return v / (1.0f + __expf(-v));
}

__device__ __forceinline__ uint32_t smem_u32(const void* p) {
    uint32_t a;
    asm("{ .reg .u64 t; cvta.to.shared.u64 t, %1; cvt.u32.u64 %0, t; }"
        : "=r"(a) : "l"(p));
    return a;
}
__device__ __forceinline__ void ldsm_x4(uint32_t& a0, uint32_t& a1,
                                        uint32_t& a2, uint32_t& a3, uint32_t addr) {
    asm volatile("ldmatrix.sync.aligned.m8n8.x4.shared.b16 {%0,%1,%2,%3}, [%4];"
        : "=r"(a0), "=r"(a1), "=r"(a2), "=r"(a3) : "r"(addr));
}
__device__ __forceinline__ void mma_bf16(float* d, uint32_t a0, uint32_t a1,
                                         uint32_t a2, uint32_t a3,
                                         uint32_t b0, uint32_t b1) {
    asm volatile(
        "mma.sync.aligned.m16n8k16.row.col.f32.bf16.bf16.f32 "
        "{%0,%1,%2,%3}, {%4,%5,%6,%7}, {%8,%9}, {%0,%1,%2,%3};"
        : "+f"(d[0]), "+f"(d[1]), "+f"(d[2]), "+f"(d[3])
        : "r"(a0), "r"(a1), "r"(a2), "r"(a3), "r"(b0), "r"(b1));
}
__device__ __forceinline__ void red_add_v2(float* ptr, float v0, float v1) {
    asm volatile("red.global.add.v2.f32 [%0], {%1,%2};"
        :: "l"(ptr), "f"(v0), "f"(v1) : "memory");
}

// ---------------- init: ln1 | zero | prepB (fused, 3 branches) --------------
__global__ __launch_bounds__(256) void init_kernel(
    const float* __restrict__ h, const float* __restrict__ g1,
    const float* __restrict__ b1, const float* __restrict__ We2)
{
    int b = blockIdx.x;
    int t = threadIdx.x;
    if (b < 1250) {
        int w = t >> 5, l = t & 31;
        int r = b * 8 + w;
        const float4 v = *(const float4*)&h[(size_t)r * CC + l * 4];
        float s  = v.x + v.y + v.z + v.w;
        float s2 = fmaf(v.x, v.x, fmaf(v.y, v.y, fmaf(v.z, v.z, v.w * v.w)));
#pragma unroll
        for (int o = 16; o; o >>= 1) {
            s  += __shfl_xor_sync(0xffffffffu, s,  o);
            s2 += __shfl_xor_sync(0xffffffffu, s2, o);
        }
        float mu   = s * (1.0f / CC);
        float var  = s2 * (1.0f / CC) - mu * mu;
        float rstd = rsqrtf(var + 1e-5f);
        float4 g  = *(const float4*)&g1[l * 4];
        float4 bb = *(const float4*)&b1[l * 4];
        float4 o;
        o.x = (v.x - mu) * rstd * g.x + bb.x;
        o.y = (v.y - mu) * rstd * g.y + bb.y;
        o.z = (v.z - mu) * rstd * g.z + bb.z;
        o.w = (v.w - mu) * rstd * g.w + bb.w;
        *(float4*)&g_hn[(size_t)r * CC + l * 4] = o;
    } else if (b < 11250) {
        int idx = (b - 1250) * 256 + t;          // exactly NN*HH
        g_msum[idx] = 0.0f;
        if (idx < NN) g_cnt[idx] = 0.0f;
    } else {
        int idx = (b - 11250) * 256 + t;         // 65536
        int n = idx >> 8, k = idx & 255;
        g_Bbf[n * HH + k] = __float2bfloat16(We2[(size_t)k * HH + n]);
    }
}

// ---------------- pre: PAB = hn @ We1 halves (FFMA, proven 41us) ------------
__global__ __launch_bounds__(256) void pre_kernel(const float* __restrict__ We1)
{
    __shared__ float s_in[CC][33];
    int t = threadIdx.x;
    int nb = blockIdx.x * 32;
    int half = blockIdx.y;
#pragma unroll
    for (int it = 0; it < 16; it++) {
        int idx = t + 256 * it;
        int e = idx >> 7, k = idx & 127;
        int n = nb + e; if (n >= NN) n = NN - 1;
        s_in[k][e] = g_hn[(size_t)n * CC + k];
    }
    __syncthreads();
    int j0 = (t & 63) * 4, e0 = (t >> 6) * 8;
    const float* Wp = We1 + (size_t)half * (128 * 256) + j0;
    float acc[8][4];
#pragma unroll
    for (int i = 0; i < 8; i++)
#pragma unroll
        for (int j = 0; j < 4; j++) acc[i][j] = 0.0f;
#pragma unroll 4
    for (int k = 0; k < CC; k++) {
        float4 w = *(const float4*)(Wp + (size_t)k * 256);
        float in[8];
#pragma unroll
        for (int i = 0; i < 8; i++) in[i] = s_in[k][e0 + i];
#pragma unroll
        for (int i = 0; i < 8; i++) {
            acc[i][0] += in[i] * w.x;
            acc[i][1] += in[i] * w.y;
            acc[i][2] += in[i] * w.z;
            acc[i][3] += in[i] * w.w;
        }
    }
#pragma unroll
    for (int i = 0; i < 8; i++) {
        int n = nb + e0 + i;
        if (n < NN) {
            float4 o; o.x = acc[i][0]; o.y = acc[i][1]; o.z = acc[i][2]; o.w = acc[i][3];
            *(float4*)&g_PAB[(size_t)n * 512 + half * 256 + j0] = o;
        }
    }
}

// ---------------- edgef: fused layer1 + GEMM + scatter ----------------------
// 64 edges/block, 256 threads (8 warps). Layer-1 writes A tile (pitch 528)
// straight to SMEM; q-loop over B quarters: copy -> ldsm/mma -> scatter.
// No global m1 intermediate.
#define PB 528
#define SA_OFF 0                           // 64*528 = 33792
#define SB_OFF 33792                       // 64*528 = 33792
#define M_OFF  67584                       // row[64] col[64] d[64] cc[64] be2[256]
#define EF_SMEM (M_OFF + 64 * 16 + 1024)   // 69632

extern __shared__ char smx[];

__global__ __launch_bounds__(256, 3) void edgef_kernel(
    const float* __restrict__ x, const int* __restrict__ ei,
    const float* __restrict__ We1, const float* __restrict__ be1,
    const float* __restrict__ be2)
{
    char* smem = smx;
    uint32_t smem_base = smem_u32(smem);
    int t = threadIdx.x;
    int wid = t >> 5, lid = t & 31;
    int eb = blockIdx.x * 64;              // 5000 * 64 = 320000 exactly

    int*   s_row = (int*)(smem + M_OFF);
    int*   s_col = s_row + 64;
    float* s_d   = (float*)(s_col + 64);
    float* s_cc  = s_d + 64;
    float* s_be2 = s_cc + 64;

    if (t < 64) {
        int e = eb + t;
        int r = ei[e], c = ei[EE + e];
        s_row[t] = r; s_col[t] = c;
        float dx = x[3 * r + 0] - x[3 * c + 0];
        float dy = x[3 * r + 1] - x[3 * c + 1];
        float dz = x[3 * r + 2] - x[3 * c + 2];
        float d = sqrtf(dx * dx + dy * dy + dz * dz);
        s_d[t] = d;
        float cc = (d <= 5.0f) ? 0.5f * (__cosf(d * 0.62831853071795864f) + 1.0f) : 0.0f;
        s_cc[t] = cc;
        atomicAdd(&g_cnt[c], 1.0f);
    }
    s_be2[t] = be2[t];
    __syncthreads();

    // ---- layer 1: thread owns colpair cp for 32 edges; STS.32 into A tile ----
    {
        int cp = t & 127;
        int p2 = cp * 2;
        int eh = (t >> 7) * 32;
        float wl0 = We1[65536 + p2], wl1 = We1[65536 + p2 + 1];
        float bb0 = be1[p2],         bb1 = be1[p2 + 1];
#pragma unroll 4
        for (int e = eh; e < eh + 32; e++) {
            int r = s_row[e], c = s_col[e];
            float2 pa = *(const float2*)&g_PAB[(size_t)r * 512 + p2];
            float2 pb = *(const float2*)&g_PAB[(size_t)c * 512 + 256 + p2];
            float dd = s_d[e];
            float u0 = silu_f(pa.x + pb.x + dd * wl0 + bb0);
            float u1 = silu_f(pa.y + pb.y + dd * wl1 + bb1);
            uint32_t pk;
            asm("cvt.rn.bf16x2.f32 %0, %1, %2;" : "=r"(pk) : "f"(u1), "f"(u0));
            *(uint32_t*)(smem + SA_OFF + e * PB + cp * 4) = pk;  // consecutive cp -> conflict-free
        }
    }
    __syncthreads();

    // ---- GEMM phase: warp (wid&3)=M-tile of 16 edges, (wid>>2)=N-half of 32 ----
    int mt = wid & 3;
    int nh = wid >> 2;
    uint32_t a_base = smem_base + SA_OFF
                    + (uint32_t)(mt * 16 + ((lid >> 3) & 1) * 8 + (lid & 7)) * PB
                    + (uint32_t)((lid >> 4) & 1) * 16;
    uint32_t b_lane = (uint32_t)((lid & 7) + ((lid >> 4) & 1) * 8) * PB
                    + (uint32_t)((lid >> 3) & 1) * 16;
    int row0 = mt * 16 + (lid >> 2), row1 = row0 + 8;
    float cc0 = s_cc[row0], cc1 = s_cc[row1];
    int   c0  = s_col[row0], c1 = s_col[row1];
    int   q2  = (lid & 3) * 2;

    for (int q = 0; q < 4; q++) {
        // copy B quarter q: rows [64q, 64q+64) x 512B (2048 int4)
        {
            const int4* src = (const int4*)g_Bbf + (size_t)q * 64 * 32;
            for (int i = t; i < 2048; i += 256)
                *(int4*)(smem + SB_OFF + (i >> 5) * PB + (i & 31) * 16) = src[i];
        }
        __syncthreads();

        float acc[4][4];
#pragma unroll
        for (int nt = 0; nt < 4; nt++)
#pragma unroll
            for (int j = 0; j < 4; j++) acc[nt][j] = 0.0f;

        uint32_t b_base4 = smem_base + SB_OFF + (uint32_t)(nh * 32) * PB + b_lane;
#pragma unroll 4
        for (int kk = 0; kk < 16; kk++) {
            uint32_t a0, a1, a2, a3;
            ldsm_x4(a0, a1, a2, a3, a_base + kk * 32);
            uint32_t bk = b_base4 + kk * 32;
#pragma unroll
            for (int nt2 = 0; nt2 < 2; nt2++) {
                uint32_t b0, b1, b2, b3;
                ldsm_x4(b0, b1, b2, b3, bk + (uint32_t)nt2 * 16 * PB);
                mma_bf16(acc[2 * nt2],     a0, a1, a2, a3, b0, b1);
                mma_bf16(acc[2 * nt2 + 1], a0, a1, a2, a3, b2, b3);
            }
        }

        // epilogue: silu(+bias)*cc, vector red.v2 scatter
        int nbase = q * 64 + nh * 32;
#pragma unroll
        for (int nt = 0; nt < 4; nt++) {
            int gcol = nbase + nt * 8 + q2;
            float bv0 = s_be2[gcol], bv1 = s_be2[gcol + 1];
            if (cc0 != 0.0f) {
                red_add_v2(&g_msum[(size_t)c0 * HH + gcol],
                           silu_f(acc[nt][0] + bv0) * cc0,
                           silu_f(acc[nt][1] + bv1) * cc0);
            }
            if (cc1 != 0.0f) {
                red_add_v2(&g_msum[(size_t)c1 * HH + gcol],
                           silu_f(acc[nt][2] + bv0) * cc1,
                           silu_f(acc[nt][3] + bv1) * cc1);
            }
        }
        __syncthreads();   // protect s_B before next q overwrite
    }
}

// ---------------- node1: t1 = silu([hn, m_aggr] @ Wn1 + bn1) ----------------
__global__ __launch_bounds__(256) void node1_kernel(
    const float* __restrict__ Wn1, const float* __restrict__ bn1)
{
    __shared__ float s_in[HH][33];
    int t = threadIdx.x;
    int nb = blockIdx.x * 32;
    int j0 = (t & 63) * 4, e0 = (t >> 6) * 8;
    float acc[8][4];
#pragma unroll
    for (int i = 0; i < 8; i++)
#pragma unroll
        for (int j = 0; j < 4; j++) acc[i][j] = 0.0f;
#pragma unroll
    for (int it = 0; it < 16; it++) {
        int idx = t + 256 * it;
        int e = idx >> 7, k = idx & 127;
        int n = nb + e; if (n >= NN) n = NN - 1;
        s_in[k][e] = g_hn[(size_t)n * CC + k];
    }
    __syncthreads();
    {
        const float* Wp = Wn1 + j0;
#pragma unroll 4
        for (int k = 0; k < 128; k++) {
            float4 w = *(const float4*)(Wp + (size_t)k * 256);
            float in[8];
#pragma unroll
            for (int i = 0; i < 8; i++) in[i] = s_in[k][e0 + i];
#pragma unroll
            for (int i = 0; i < 8; i++) {
                acc[i][0] += in[i] * w.x;
                acc[i][1] += in[i] * w.y;
                acc[i][2] += in[i] * w.z;
                acc[i][3] += in[i] * w.w;
            }
        }
    }
    __syncthreads();
    for (int it = 0; it < 32; it++) {
        int n = nb + it; if (n >= NN) n = NN - 1;
        float c = g_cnt[n];
        float inv = 1.0f / fmaxf(c, 1.0f);
        s_in[t][it] = g_msum[(size_t)n * HH + t] * inv;
    }
    __syncthreads();
    {
        const float* Wp = Wn1 + 128 * 256 + j0;
#pragma unroll 4
        for (int k = 0; k < HH; k++) {
            float4 w = *(const float4*)(Wp + (size_t)k * 256);
            float in[8];
#pragma unroll
            for (int i = 0; i < 8; i++) in[i] = s_in[k][e0 + i];
#pragma unroll
            for (int i = 0; i < 8; i++) {
                acc[i][0] += in[i] * w.x;
                acc[i][1] += in[i] * w.y;
                acc[i][2] += in[i] * w.z;
                acc[i][3] += in[i] * w.w;
            }
        }
    }
    float4 b = *(const float4*)(bn1 + j0);
#pragma unroll
    for (int i = 0; i < 8; i++) {
        int n = nb + e0 + i;
        if (n < NN) {
            float4 o;
            o.x = silu_f(acc[i][0] + b.x);
            o.y = silu_f(acc[i][1] + b.y);
            o.z = silu_f(acc[i][2] + b.z);
            o.w = silu_f(acc[i][3] + b.w);
            *(float4*)&g_t1[(size_t)n * HH + j0] = o;
        }
    }
}

// ---------------- node2 ----------------
__global__ __launch_bounds__(256) void node2_kernel(
    const float* __restrict__ h, const float* __restrict__ Wn2,
    const float* __restrict__ bn2, const float* __restrict__ g2,
    const float* __restrict__ beta2)
{
    __shared__ float s_in[HH][33];
    int t = threadIdx.x;
    int nb = blockIdx.x * 32;
    for (int it = 0; it < 32; it++) {
        int n = nb + it; if (n >= NN) n = NN - 1;
        s_in[t][it] = g_t1[(size_t)n * HH + t];
    }
    __syncthreads();
    int j0 = (t & 31) * 4, e0 = (t >> 5) * 4;
    float acc[4][4];
#pragma unroll
    for (int i = 0; i < 4; i++)
#pragma unroll
        for (int j = 0; j < 4; j++) acc[i][j] = 0.0f;
    const float* Wp = Wn2 + j0;
#pragma unroll 4
    for (int k = 0; k < HH; k++) {
        float4 w = *(const float4*)(Wp + (size_t)k * CC);
        float in[4];
#pragma unroll
        for (int i = 0; i < 4; i++) in[i] = s_in[k][e0 + i];
#pragma unroll
        for (int i = 0; i < 4; i++) {
            acc[i][0] += in[i] * w.x;
            acc[i][1] += in[i] * w.y;
            acc[i][2] += in[i] * w.z;
            acc[i][3] += in[i] * w.w;
        }
    }
    float4 b  = *(const float4*)(bn2 + j0);
    float4 gg = *(const float4*)(g2 + j0);
    float4 be = *(const float4*)(beta2 + j0);
#pragma unroll
    for (int i = 0; i < 4; i++) {
        int n = nb + e0 + i;
        bool valid = (n < NN);
        int nc = valid ? n : (NN - 1);
        float4 hv  = *(const float4*)&h[(size_t)nc * CC + j0];
        float4 hnv = *(const float4*)&g_hn[(size_t)nc * CC + j0];
        float v0 = hv.x + hnv.x + acc[i][0] + b.x;
        float v1 = hv.y + hnv.y + acc[i][1] + b.y;
        float v2 = hv.z + hnv.z + acc[i][2] + b.z;
        float v3 = hv.w + hnv.w + acc[i][3] + b.w;
        float s  = v0 + v1 + v2 + v3;
        float s2 = fmaf(v0, v0, fmaf(v1, v1, fmaf(v2, v2, v3 * v3)));
#pragma unroll
        for (int o = 16; o; o >>= 1) {
            s  += __shfl_xor_sync(0xffffffffu, s,  o);
            s2 += __shfl_xor_sync(0xffffffffu, s2, o);
        }
        float mu   = s * (1.0f / CC);
        float var  = s2 * (1.0f / CC) - mu * mu;
        float rstd = rsqrtf(var + 1e-5f);
        if (valid) {
            float4 h1v; h1v.x = v0; h1v.y = v1; h1v.z = v2; h1v.w = v3;
            *(float4*)&g_h1[(size_t)n * CC + j0] = h1v;
            float4 o;
            o.x = (v0 - mu) * rstd * gg.x + be.x;
            o.y = (v1 - mu) * rstd * gg.y + be.y;
            o.z = (v2 - mu) * rstd * gg.z + be.z;
            o.w = (v3 - mu) * rstd * gg.w + be.w;
            *(float4*)&g_h2n[(size_t)n * CC + j0] = o;
        }
    }
}

// ---------------- node3 ----------------
__global__ __launch_bounds__(256) void node3_kernel(
    const float* __restrict__ Wm1, const float* __restrict__ bm1)
{
    __shared__ float s_in[CC][33];
    int t = threadIdx.x;
    int nb = blockIdx.x * 32;
#pragma unroll
    for (int it = 0; it < 16; it++) {
        int idx = t + 256 * it;
        int e = idx >> 7, k = idx & 127;
        int n = nb + e; if (n >= NN) n = NN - 1;
        s_in[k][e] = g_h2n[(size_t)n * CC + k];
    }
    __syncthreads();
    int j0 = (t & 63) * 4, e0 = (t >> 6) * 8;
    float acc[8][4];
#pragma unroll
    for (int i = 0; i < 8; i++)
#pragma unroll
        for (int j = 0; j < 4; j++) acc[i][j] = 0.0f;
    const float* Wp = Wm1 + j0;
#pragma unroll 4
    for (int k = 0; k < CC; k++) {
        float4 w = *(const float4*)(Wp + (size_t)k * HH);
        float in[8];
#pragma unroll
        for (int i = 0; i < 8; i++) in[i] = s_in[k][e0 + i];
#pragma unroll
        for (int i = 0; i < 8; i++) {
            acc[i][0] += in[i] * w.x;
            acc[i][1] += in[i] * w.y;
            acc[i][2] += in[i] * w.z;
            acc[i][3] += in[i] * w.w;
        }
    }
    float4 b = *(const float4*)(bm1 + j0);
#pragma unroll
    for (int i = 0; i < 8; i++) {
        int n = nb + e0 + i;
        if (n < NN) {
            float4 o;
            o.x = silu_f(acc[i][0] + b.x);
            o.y = silu_f(acc[i][1] + b.y);
            o.z = silu_f(acc[i][2] + b.z);
            o.w = silu_f(acc[i][3] + b.w);
            *(float4*)&g_t2[(size_t)n * HH + j0] = o;
        }
    }
}

// ---------------- node4 ----------------
__global__ __launch_bounds__(256) void node4_kernel(
    const float* __restrict__ Wm2, const float* __restrict__ bm2,
    float* __restrict__ out)
{
    __shared__ float s_in[HH][33];
    int t = threadIdx.x;
    int nb = blockIdx.x * 32;
    for (int it = 0; it < 32; it++) {
        int n = nb + it; if (n >= NN) n = NN - 1;
        s_in[t][it] = g_t2[(size_t)n * HH + t];
    }
    __syncthreads();
    int j0 = (t & 31) * 4, e0 = (t >> 5) * 4;
    float acc[4][4];
#pragma unroll
    for (int i = 0; i < 4; i++)
#pragma unroll
        for (int j = 0; j < 4; j++) acc[i][j] = 0.0f;
    const float* Wp = Wm2 + j0;
#pragma unroll 4
    for (int k = 0; k < HH; k++) {
        float4 w = *(const float4*)(Wp + (size_t)k * CC);
        float in[4];
#pragma unroll
        for (int i = 0; i < 4; i++) in[i] = s_in[k][e0 + i];
#pragma unroll
        for (int i = 0; i < 4; i++) {
            acc[i][0] += in[i] * w.x;
            acc[i][1] += in[i] * w.y;
            acc[i][2] += in[i] * w.z;
            acc[i][3] += in[i] * w.w;
        }
    }
    float4 b = *(const float4*)(bm2 + j0);
#pragma unroll
    for (int i = 0; i < 4; i++) {
        int n = nb + e0 + i;
        if (n < NN) {
            float4 h1v = *(const float4*)&g_h1[(size_t)n * CC + j0];
            float4 o;
            o.x = h1v.x + acc[i][0] + b.x;
            o.y = h1v.y + acc[i][1] + b.y;
            o.z = h1v.z + acc[i][2] + b.z;
            o.w = h1v.w + acc[i][3] + b.w;
            *(float4*)&out[(size_t)n * CC + j0] = o;
        }
    }
}

// ---------------- launch ----------------
extern "C" void kernel_launch(void* const* d_in, const int* in_sizes, int n_in,
                              void* d_out, int out_size)
{
    const float* x     = (const float*)d_in[0];
    const float* h     = (const float*)d_in[1];
    const int*   ei    = (const int*)d_in[2];
    const float* We1   = (const float*)d_in[3];
    const float* be1   = (const float*)d_in[4];
    const float* We2   = (const float*)d_in[5];
    const float* be2   = (const float*)d_in[6];
    const float* Wn1   = (const float*)d_in[7];
    const float* bn1   = (const float*)d_in[8];
    const float* Wn2   = (const float*)d_in[9];
    const float* bn2   = (const float*)d_in[10];
    const float* Wm1   = (const float*)d_in[11];
    const float* bm1   = (const float*)d_in[12];
    const float* Wm2   = (const float*)d_in[13];
    const float* bm2   = (const float*)d_in[14];
    const float* g1    = (const float*)d_in[15];
    const float* beta1 = (const float*)d_in[16];
    const float* g2    = (const float*)d_in[17];
    const float* beta2 = (const float*)d_in[18];
    float* out = (float*)d_out;

    static int smem_set = 0;
    if (!smem_set) {
        cudaFuncSetAttribute(edgef_kernel,
                             cudaFuncAttributeMaxDynamicSharedMemorySize, EF_SMEM);
        smem_set = 1;
    }

    int nblk = (NN + 31) / 32;  // 313

    init_kernel<<<11506, 256>>>(h, g1, beta1, We2);
    pre_kernel<<<dim3(nblk, 2), 256>>>(We1);
    edgef_kernel<<<EE / 64, 256, EF_SMEM>>>(x, ei, We1, be1, be2);
    node1_kernel<<<nblk, 256>>>(Wn1, bn1);
    node2_kernel<<<nblk, 256>>>(h, Wn2, bn2, g2, beta2);
    node3_kernel<<<nblk, 256>>>(Wm1, bm1);
    node4_kernel<<<nblk, 256>>>(Wm2, bm2, out);
}